// round 3
// baseline (speedup 1.0000x reference)
#include <cuda_runtime.h>
#include <cuda_bf16.h>

// Problem constants (from reference): N=50000 nodes, E=1.6M edges, D_in=D_out=128.
#define D 128
#define D4 (D / 4)            // 32 float4 per row
#define MAX_NODES 50048       // 50000 rounded up to 64
#define K_TOT 256             // concat [feat ; h_neigh]
#define BM 64                 // nodes per block in GEMM
#define WT_STRIDE 132         // padded row stride for transposed weights (conflict mitigation, float4-aligned)

// ---------------- scratch (device globals; no allocation allowed) ----------------
__device__ float g_agg[MAX_NODES * D];   // neighbor sum, [N,128]
__device__ float g_deg[MAX_NODES];       // in-degree (float)

// ---------------- kernel 1: zero scratch ----------------
__global__ void zero_kernel(int n4_agg, int n_deg) {
    float4 z4 = make_float4(0.f, 0.f, 0.f, 0.f);
    float4* a4 = reinterpret_cast<float4*>(g_agg);
    int stride = gridDim.x * blockDim.x;
    for (int i = blockIdx.x * blockDim.x + threadIdx.x; i < n4_agg; i += stride)
        a4[i] = z4;
    for (int i = blockIdx.x * blockDim.x + threadIdx.x; i < n_deg; i += stride)
        g_deg[i] = 0.f;
}

// ---------------- kernel 2: edge scatter (warp per edge) ----------------
// Each warp handles one edge: 32 lanes x float4 = 128 floats gather + vector atomic add.
__global__ void scatter_kernel(const float* __restrict__ feat,
                               const int* __restrict__ src,
                               const int* __restrict__ dst,
                               int n_edges) {
    int warp_id = (blockIdx.x * blockDim.x + threadIdx.x) >> 5;
    if (warp_id >= n_edges) return;
    int lane = threadIdx.x & 31;

    int s = __ldg(&src[warp_id]);   // broadcast within warp (single sector)
    int d = __ldg(&dst[warp_id]);

    const float4* f4 = reinterpret_cast<const float4*>(feat) + (size_t)s * D4 + lane;
    float4 v = __ldg(f4);

    float4* a4 = reinterpret_cast<float4*>(g_agg) + (size_t)d * D4 + lane;
    atomicAdd(a4, v);               // RED.ADD.F32x4 (sm_90+)

    if (lane == 0) atomicAdd(&g_deg[d], 1.0f);
}

// ---------------- kernel 3: fused mean + dual-linear GEMM ----------------
// out[n,:] = (b_self + b_neigh) + z[n,:] @ Wcat^T
//   z[n,0:128]   = feat[n,:]
//   z[n,128:256] = agg[n,:] / max(deg[n],1)
//   Wcat[o,0:128] = W_self[o,:], Wcat[o,128:256] = W_neigh[o,:]
// Block: 64 nodes x 128 out-cols. 256 threads; each thread 8 nodes x 4 cols.
__global__ void gemm_kernel(const float* __restrict__ feat,
                            const float* __restrict__ W_self,
                            const float* __restrict__ b_self,
                            const float* __restrict__ W_neigh,
                            const float* __restrict__ b_neigh,
                            float* __restrict__ out,
                            int n_nodes) {
    extern __shared__ float smem[];
    float* Wt = smem;                         // [K_TOT][WT_STRIDE] transposed weights
    float* Zs = smem + K_TOT * WT_STRIDE;     // [BM][K_TOT]

    const int tid = threadIdx.x;
    const int base = blockIdx.x * BM;

    // --- stage transposed weights: Wt[k][o] = W[o][k] ---
    for (int i = tid; i < D * D; i += blockDim.x) {
        int o = i >> 7;          // row of W (output)
        int k = i & (D - 1);     // col of W (input)
        Wt[k * WT_STRIDE + o]           = W_self[i];
        Wt[(k + D) * WT_STRIDE + o]     = W_neigh[i];
    }

    // --- stage Z tile: [feat ; agg/deg] ---
    const float4* feat4 = reinterpret_cast<const float4*>(feat);
    const float4* agg4  = reinterpret_cast<const float4*>(g_agg);
    float4* Zs4 = reinterpret_cast<float4*>(Zs);
    for (int i = tid; i < BM * D4; i += blockDim.x) {
        int r  = i >> 5;         // node row within tile
        int c4 = i & 31;         // float4 column
        int n = base + r;
        float4 f = make_float4(0.f, 0.f, 0.f, 0.f);
        float4 a = f;
        if (n < n_nodes) {
            f = __ldg(&feat4[(size_t)n * D4 + c4]);
            float4 araw = agg4[(size_t)n * D4 + c4];
            float inv = 1.0f / fmaxf(g_deg[n], 1.0f);
            a.x = araw.x * inv; a.y = araw.y * inv;
            a.z = araw.z * inv; a.w = araw.w * inv;
        }
        Zs4[r * (K_TOT / 4) + c4]       = f;   // cols [0,128)
        Zs4[r * (K_TOT / 4) + 32 + c4]  = a;   // cols [128,256)
    }
    __syncthreads();

    // --- register micro-tile: thread -> (trow: 8 nodes, tcol: 4 cols) ---
    const int tcol = tid & 31;       // 32 col-groups
    const int trow = tid >> 5;       // 8 row-groups
    const int c0 = tcol * 4;

    float acc[8][4];
    #pragma unroll
    for (int i = 0; i < 8; i++)
        #pragma unroll
        for (int j = 0; j < 4; j++) acc[i][j] = 0.f;

    #pragma unroll 2
    for (int k = 0; k < K_TOT; k += 4) {
        float4 w0 = *reinterpret_cast<const float4*>(&Wt[(k + 0) * WT_STRIDE + c0]);
        float4 w1 = *reinterpret_cast<const float4*>(&Wt[(k + 1) * WT_STRIDE + c0]);
        float4 w2 = *reinterpret_cast<const float4*>(&Wt[(k + 2) * WT_STRIDE + c0]);
        float4 w3 = *reinterpret_cast<const float4*>(&Wt[(k + 3) * WT_STRIDE + c0]);
        #pragma unroll
        for (int i = 0; i < 8; i++) {
            float4 z = *reinterpret_cast<const float4*>(&Zs[(trow * 8 + i) * K_TOT + k]);
            acc[i][0] += z.x * w0.x; acc[i][1] += z.x * w0.y;
            acc[i][2] += z.x * w0.z; acc[i][3] += z.x * w0.w;
            acc[i][0] += z.y * w1.x; acc[i][1] += z.y * w1.y;
            acc[i][2] += z.y * w1.z; acc[i][3] += z.y * w1.w;
            acc[i][0] += z.z * w2.x; acc[i][1] += z.z * w2.y;
            acc[i][2] += z.z * w2.z; acc[i][3] += z.z * w2.w;
            acc[i][0] += z.w * w3.x; acc[i][1] += z.w * w3.y;
            acc[i][2] += z.w * w3.z; acc[i][3] += z.w * w3.w;
        }
    }

    // --- epilogue: bias add + store ---
    float4 bs = *reinterpret_cast<const float4*>(&b_self[c0]);
    float4 bn = *reinterpret_cast<const float4*>(&b_neigh[c0]);
    float4 bias = make_float4(bs.x + bn.x, bs.y + bn.y, bs.z + bn.z, bs.w + bn.w);

    float4* out4 = reinterpret_cast<float4*>(out);
    #pragma unroll
    for (int i = 0; i < 8; i++) {
        int n = base + trow * 8 + i;
        if (n < n_nodes) {
            float4 o = make_float4(acc[i][0] + bias.x, acc[i][1] + bias.y,
                                   acc[i][2] + bias.z, acc[i][3] + bias.w);
            out4[(size_t)n * D4 + tcol] = o;
        }
    }
}

// ---------------- launch ----------------
extern "C" void kernel_launch(void* const* d_in, const int* in_sizes, int n_in,
                              void* d_out, int out_size) {
    const float* feat    = (const float*)d_in[0];
    const int*   src     = (const int*)  d_in[1];
    const int*   dst     = (const int*)  d_in[2];
    const float* W_self  = (const float*)d_in[3];
    const float* b_self  = (const float*)d_in[4];
    const float* W_neigh = (const float*)d_in[5];
    const float* b_neigh = (const float*)d_in[6];
    float* out = (float*)d_out;

    const int n_nodes = in_sizes[0] / D;
    const int n_edges = in_sizes[1];

    // 1. zero scratch
    {
        int n4 = n_nodes * D4;
        int blocks = 2048;
        zero_kernel<<<blocks, 256>>>(n4, n_nodes);
    }

    // 2. edge scatter: warp per edge
    {
        int warps_per_block = 256 / 32;
        int blocks = (n_edges + warps_per_block - 1) / warps_per_block;
        scatter_kernel<<<blocks, 256>>>(feat, src, dst, n_edges);
    }

    // 3. fused GEMM
    {
        size_t smem = (size_t)(K_TOT * WT_STRIDE + BM * K_TOT) * sizeof(float); // 200704 B
        cudaFuncSetAttribute(gemm_kernel,
                             cudaFuncAttributeMaxDynamicSharedMemorySize, (int)smem);
        int blocks = (n_nodes + BM - 1) / BM;
        gemm_kernel<<<blocks, 256, smem>>>(feat, W_self, b_self, W_neigh, b_neigh,
                                           out, n_nodes);
    }
}

// round 6
// speedup vs baseline: 1.4010x; 1.4010x over previous
#include <cuda_runtime.h>
#include <cuda_bf16.h>

// Problem constants: N=50000 nodes, E=1.6M edges, D_in=D_out=128.
#define D 128
#define D4 (D / 4)              // 32 float4 per row
#define MAX_NODES 50048         // 50000 rounded up to 64
#define CAP 128                 // bucket capacity per node (Poisson(32); overflow ~1e-30)
#define K_TOT 256               // concat [feat ; mean_neigh]
#define BM 64                   // nodes per block in GEMM
#define WT_STRIDE 132           // padded row stride, transposed weights (float4-aligned)
#define ZT_STRIDE 68            // padded row stride, transposed Z (16B-aligned rows: 68*4=272 % 16 == 0)

// ---------------- scratch (device globals; no allocation allowed) ----------------
__device__ float g_agg[MAX_NODES * D];        // neighbor mean (also overflow-fallback sums)
__device__ int   g_cnt[MAX_NODES];            // in-degree counters
__device__ int   g_bucket[MAX_NODES * CAP];   // per-node neighbor src ids

// ---------------- packed f32x2 helpers ----------------
__device__ __forceinline__ unsigned long long pack2_dup(float x) {
    unsigned long long r;
    asm("mov.b64 %0, {%1, %1};" : "=l"(r) : "f"(x));
    return r;
}
__device__ __forceinline__ void ffma2(unsigned long long& acc,
                                      unsigned long long a, unsigned long long b) {
    asm("fma.rn.f32x2 %0, %1, %2, %0;" : "+l"(acc) : "l"(a), "l"(b));
}
__device__ __forceinline__ void unpack2(unsigned long long v, float& lo, float& hi) {
    asm("mov.b64 {%0, %1}, %2;" : "=f"(lo), "=f"(hi) : "l"(v));
}

// ---------------- kernel 1: zero scratch (agg for fallback path + counters) ----------------
__global__ void zero_kernel(int n4_agg, int n_cnt) {
    float4 z4 = make_float4(0.f, 0.f, 0.f, 0.f);
    float4* a4 = reinterpret_cast<float4*>(g_agg);
    int stride = gridDim.x * blockDim.x;
    for (int i = blockIdx.x * blockDim.x + threadIdx.x; i < n4_agg; i += stride)
        a4[i] = z4;
    for (int i = blockIdx.x * blockDim.x + threadIdx.x; i < n_cnt; i += stride)
        g_cnt[i] = 0;
}

// ---------------- kernel 2: fill per-dst buckets with src ids ----------------
__global__ void fill_kernel(const float* __restrict__ feat,
                            const int* __restrict__ src,
                            const int* __restrict__ dst,
                            int n_edges) {
    int e = blockIdx.x * blockDim.x + threadIdx.x;
    if (e >= n_edges) return;
    int s = src[e];
    int d = dst[e];
    int pos = atomicAdd(&g_cnt[d], 1);
    if (pos < CAP) {
        g_bucket[d * CAP + pos] = s;
    } else {
        // essentially-never fallback: atomic push of the full row
        const float4* f4 = reinterpret_cast<const float4*>(feat) + (size_t)s * D4;
        float4* a4 = reinterpret_cast<float4*>(g_agg) + (size_t)d * D4;
        #pragma unroll
        for (int i = 0; i < D4; i++) atomicAdd(&a4[i], f4[i]);
    }
}

// ---------------- kernel 3: warp-per-node pull aggregation (no float atomics) ----------------
__global__ void aggregate_kernel(const float* __restrict__ feat, int n_nodes) {
    int w = (blockIdx.x * blockDim.x + threadIdx.x) >> 5;
    if (w >= n_nodes) return;
    int lane = threadIdx.x & 31;

    int c = g_cnt[w];
    int m = min(c, CAP);

    const float4* f4 = reinterpret_cast<const float4*>(feat);
    float4* a4 = reinterpret_cast<float4*>(g_agg);

    float4 acc = a4[(size_t)w * D4 + lane];   // overflow-fallback partial (normally 0)
    const int* bk = &g_bucket[w * CAP];

    for (int i0 = 0; i0 < m; i0 += 32) {
        int take = min(32, m - i0);
        int my = (lane < take) ? bk[i0 + lane] : 0;
        #pragma unroll 4
        for (int j = 0; j < take; j++) {
            int s = __shfl_sync(0xffffffffu, my, j);
            float4 v = __ldg(&f4[(size_t)s * D4 + lane]);
            acc.x += v.x; acc.y += v.y; acc.z += v.z; acc.w += v.w;
        }
    }

    float inv = 1.0f / fmaxf((float)c, 1.0f);
    acc.x *= inv; acc.y *= inv; acc.z *= inv; acc.w *= inv;
    a4[(size_t)w * D4 + lane] = acc;          // store the MEAN
}

// ---------------- kernel 4: fused dual-linear GEMM with packed f32x2 FMA ----------------
// out[n,:] = (b_self + b_neigh) + [feat[n] ; mean[n]] @ [W_self ; W_neigh]^T
// Block: 64 nodes x 128 cols, 256 threads, thread tile = 8 rows x 4 cols.
// Rows are packed in f32x2 pairs; weights duplicated into both halves.
__global__ void gemm_kernel(const float* __restrict__ feat,
                            const float* __restrict__ W_self,
                            const float* __restrict__ b_self,
                            const float* __restrict__ W_neigh,
                            const float* __restrict__ b_neigh,
                            float* __restrict__ out,
                            int n_nodes) {
    extern __shared__ float smem[];
    float* Wt = smem;                          // [K_TOT][WT_STRIDE]  transposed weights
    float* Zt = smem + K_TOT * WT_STRIDE;      // [K_TOT][ZT_STRIDE]  transposed Z tile

    const int tid = threadIdx.x;
    const int base = blockIdx.x * BM;

    // --- stage transposed weights: Wt[k][o] = W[o][k] ---
    for (int i = tid; i < D * D; i += blockDim.x) {
        int o = i >> 7;
        int k = i & (D - 1);
        Wt[k * WT_STRIDE + o]       = W_self[i];
        Wt[(k + D) * WT_STRIDE + o] = W_neigh[i];
    }

    // --- stage Z transposed: Zt[k][r] ; lanes vary in r -> conflict-free smem writes ---
    const float4* feat4 = reinterpret_cast<const float4*>(feat);
    const float4* agg4  = reinterpret_cast<const float4*>(g_agg);
    for (int i = tid; i < BM * D4; i += blockDim.x) {
        int r  = i & 63;          // node row in tile (lane-varying)
        int c4 = i >> 6;          // float4 column
        int n = base + r;
        float4 f = make_float4(0.f, 0.f, 0.f, 0.f);
        float4 a = f;
        if (n < n_nodes) {
            f = __ldg(&feat4[(size_t)n * D4 + c4]);
            a = agg4[(size_t)n * D4 + c4];     // already the mean
        }
        int k = c4 * 4;
        Zt[(k + 0) * ZT_STRIDE + r] = f.x;
        Zt[(k + 1) * ZT_STRIDE + r] = f.y;
        Zt[(k + 2) * ZT_STRIDE + r] = f.z;
        Zt[(k + 3) * ZT_STRIDE + r] = f.w;
        Zt[(k + 0 + D) * ZT_STRIDE + r] = a.x;
        Zt[(k + 1 + D) * ZT_STRIDE + r] = a.y;
        Zt[(k + 2 + D) * ZT_STRIDE + r] = a.z;
        Zt[(k + 3 + D) * ZT_STRIDE + r] = a.w;
    }
    __syncthreads();

    const int lane = tid & 31;     // 32 col-groups
    const int trow = tid >> 5;     // 8 row-groups (warp-uniform -> Z loads broadcast)
    const int c0 = lane * 4;

    unsigned long long acc[4][4];  // [row-pair][col]
    #pragma unroll
    for (int p = 0; p < 4; p++)
        #pragma unroll
        for (int j = 0; j < 4; j++) acc[p][j] = 0ull;

    const float* zbase = &Zt[trow * 8];

    #pragma unroll 4
    for (int k = 0; k < K_TOT; k++) {
        float4 wv = *reinterpret_cast<const float4*>(&Wt[k * WT_STRIDE + c0]);
        unsigned long long wd0 = pack2_dup(wv.x);
        unsigned long long wd1 = pack2_dup(wv.y);
        unsigned long long wd2 = pack2_dup(wv.z);
        unsigned long long wd3 = pack2_dup(wv.w);

        const ulonglong2* zp = reinterpret_cast<const ulonglong2*>(zbase + k * ZT_STRIDE);
        ulonglong2 z01 = zp[0];    // row pairs (0,1),(2,3)
        ulonglong2 z23 = zp[1];    // row pairs (4,5),(6,7)

        ffma2(acc[0][0], z01.x, wd0); ffma2(acc[0][1], z01.x, wd1);
        ffma2(acc[0][2], z01.x, wd2); ffma2(acc[0][3], z01.x, wd3);
        ffma2(acc[1][0], z01.y, wd0); ffma2(acc[1][1], z01.y, wd1);
        ffma2(acc[1][2], z01.y, wd2); ffma2(acc[1][3], z01.y, wd3);
        ffma2(acc[2][0], z23.x, wd0); ffma2(acc[2][1], z23.x, wd1);
        ffma2(acc[2][2], z23.x, wd2); ffma2(acc[2][3], z23.x, wd3);
        ffma2(acc[3][0], z23.y, wd0); ffma2(acc[3][1], z23.y, wd1);
        ffma2(acc[3][2], z23.y, wd2); ffma2(acc[3][3], z23.y, wd3);
    }

    // --- epilogue: bias + store ---
    float4 bs = *reinterpret_cast<const float4*>(&b_self[c0]);
    float4 bn = *reinterpret_cast<const float4*>(&b_neigh[c0]);
    float4 bias = make_float4(bs.x + bn.x, bs.y + bn.y, bs.z + bn.z, bs.w + bn.w);

    float4* out4 = reinterpret_cast<float4*>(out);
    #pragma unroll
    for (int p = 0; p < 4; p++) {
        float lo0, hi0, lo1, hi1, lo2, hi2, lo3, hi3;
        unpack2(acc[p][0], lo0, hi0);
        unpack2(acc[p][1], lo1, hi1);
        unpack2(acc[p][2], lo2, hi2);
        unpack2(acc[p][3], lo3, hi3);
        int r0 = base + trow * 8 + 2 * p;
        if (r0 < n_nodes)
            out4[(size_t)r0 * D4 + lane] =
                make_float4(lo0 + bias.x, lo1 + bias.y, lo2 + bias.z, lo3 + bias.w);
        if (r0 + 1 < n_nodes)
            out4[(size_t)(r0 + 1) * D4 + lane] =
                make_float4(hi0 + bias.x, hi1 + bias.y, hi2 + bias.z, hi3 + bias.w);
    }
}

// ---------------- launch ----------------
extern "C" void kernel_launch(void* const* d_in, const int* in_sizes, int n_in,
                              void* d_out, int out_size) {
    const float* feat    = (const float*)d_in[0];
    const int*   src     = (const int*)  d_in[1];
    const int*   dst     = (const int*)  d_in[2];
    const float* W_self  = (const float*)d_in[3];
    const float* b_self  = (const float*)d_in[4];
    const float* W_neigh = (const float*)d_in[5];
    const float* b_neigh = (const float*)d_in[6];
    float* out = (float*)d_out;

    const int n_nodes = in_sizes[0] / D;
    const int n_edges = in_sizes[1];

    // 1. zero fallback-agg + counters
    zero_kernel<<<2048, 256>>>(n_nodes * D4, n_nodes);

    // 2. fill per-dst buckets (thread per edge)
    fill_kernel<<<(n_edges + 255) / 256, 256>>>(feat, src, dst, n_edges);

    // 3. warp-per-node pull aggregation -> g_agg holds the mean
    {
        int warps_per_block = 256 / 32;
        int blocks = (n_nodes + warps_per_block - 1) / warps_per_block;
        aggregate_kernel<<<blocks, 256>>>(feat, n_nodes);
    }

    // 4. fused GEMM (packed f32x2 FMA)
    {
        size_t smem = (size_t)(K_TOT * WT_STRIDE + K_TOT * ZT_STRIDE) * sizeof(float); // 204800 B
        cudaFuncSetAttribute(gemm_kernel,
                             cudaFuncAttributeMaxDynamicSharedMemorySize, (int)smem);
        int blocks = (n_nodes + BM - 1) / BM;
        gemm_kernel<<<blocks, 256, smem>>>(feat, W_self, b_self, W_neigh, b_neigh,
                                           out, n_nodes);
    }
}